// round 1
// baseline (speedup 1.0000x reference)
#include <cuda_runtime.h>
#include <cuda_bf16.h>

// WaveletTransform: 3-level low-pass pyramid on x[8,32,512,512] fp32.
// out = x, except per-channel:
//   out[0:256,0:256] = down2x(conv3x3(x[0:512,0:512]))        (level 0)
//   out[0:128,0:128] = down2x(conv3x3(level0 result[0:256]^2)) (level 1)
//   out[0: 64,0: 64] = down2x(conv3x3(level1 result[0:128]^2)) (level 2)
// conv kernel = outer([.25,.5,.25],[.25,.5,.25]), zero-padded 'same',
// downsample takes even indices (centers at 2i,2j -> taps 2i-1..2i+1).

#define BC_TOTAL (8 * 32)
#define H0 512
#define W0C 512

// level-1 intermediate (128x128 per channel) — scratch via device global
__device__ float g_lvl1[BC_TOTAL * 128 * 128];

__device__ __forceinline__ float hfilt(float a, float b, float c) {
    return 0.25f * a + 0.5f * b + 0.25f * c;
}

// ---------------------------------------------------------------------------
// K1: fused identity copy (float4) + level-0 conv-down into top-left 256^2.
// grid: (1, 512, 256), block: 128 threads. Each thread owns 4 consecutive
// columns (one float4). Quadrant threads (i<256, j4<64) compute 4 conv-down
// outputs sharing the 3x10 input window; others do a vectorized copy.
// ---------------------------------------------------------------------------
__global__ void __launch_bounds__(128) k1_copy_down0(
    const float* __restrict__ x, float* __restrict__ out)
{
    const int j4 = threadIdx.x;        // 0..127  (column/4)
    const int i  = blockIdx.y;         // 0..511  (row)
    const int bc = blockIdx.z;         // 0..255

    const float* xp = x   + (size_t)bc * H0 * W0C;
    float*       op = out + (size_t)bc * H0 * W0C;

    if (i < 256 && j4 < 64) {
        // output cols j = 4*j4 + q, q=0..3; input cols needed: 8*j4-1 .. 8*j4+8
        const int cbase = 8 * j4 - 1;          // may be -1 when j4 == 0
        const int r0 = 2 * i - 1;              // may be -1 when i == 0

        float acc0 = 0.f, acc1 = 0.f, acc2 = 0.f, acc3 = 0.f;
        #pragma unroll
        for (int a = 0; a < 3; a++) {
            const int r = r0 + a;              // r <= 511 always
            if (r < 0) continue;
            const float wr = (a == 1) ? 0.5f : 0.25f;
            const float* row = xp + (size_t)r * W0C;
            float v[10];
            v[0] = (cbase >= 0) ? row[cbase] : 0.f;   // zero-pad left edge
            #pragma unroll
            for (int k = 1; k < 10; k++) v[k] = row[cbase + k];  // cbase+9 <= 511
            acc0 += wr * hfilt(v[0], v[1], v[2]);
            acc1 += wr * hfilt(v[2], v[3], v[4]);
            acc2 += wr * hfilt(v[4], v[5], v[6]);
            acc3 += wr * hfilt(v[6], v[7], v[8]);
        }
        float4 res = make_float4(acc0, acc1, acc2, acc3);
        *reinterpret_cast<float4*>(op + (size_t)i * W0C + 4 * j4) = res;
    } else {
        const float4* src = reinterpret_cast<const float4*>(xp + (size_t)i * W0C) + j4;
        float4*       dst = reinterpret_cast<float4*>(op + (size_t)i * W0C) + j4;
        *dst = *src;
    }
}

// ---------------------------------------------------------------------------
// K2: level-1 conv-down. Reads out[0:256]^2 (level-0 result, fully written by
// K1), writes the 128^2 result to g_lvl1 (avoids in-place read/write race).
// grid: (1, 128, 256), block: 128.
// ---------------------------------------------------------------------------
__global__ void __launch_bounds__(128) k2_down1(const float* __restrict__ out)
{
    const int j  = threadIdx.x;   // 0..127
    const int i  = blockIdx.y;    // 0..127
    const int bc = blockIdx.z;

    const float* sp = out + (size_t)bc * H0 * W0C;   // stride 512, region 256^2
    const int r0 = 2 * i - 1;
    const int c0 = 2 * j - 1;

    float acc = 0.f;
    #pragma unroll
    for (int a = 0; a < 3; a++) {
        const int r = r0 + a;                        // <= 255
        if (r < 0) continue;
        const float wr = (a == 1) ? 0.5f : 0.25f;
        const float* row = sp + (size_t)r * W0C;
        float l = (c0 >= 0) ? row[c0] : 0.f;
        float m = row[c0 + 1];
        float rt = row[c0 + 2];                      // c0+2 <= 255
        acc += wr * hfilt(l, m, rt);
    }
    g_lvl1[(size_t)bc * 128 * 128 + (size_t)i * 128 + j] = acc;
}

// ---------------------------------------------------------------------------
// K3: level-2 conv-down + writeback of the 128^2 region into out.
// inner 64^2 = conv-down of g_lvl1; remainder = copy of g_lvl1.
// grid: (1, 128, 256), block: 128.
// ---------------------------------------------------------------------------
__global__ void __launch_bounds__(128) k3_down2(float* __restrict__ out)
{
    const int j  = threadIdx.x;   // 0..127
    const int i  = blockIdx.y;    // 0..127
    const int bc = blockIdx.z;

    const float* sp = g_lvl1 + (size_t)bc * 128 * 128;
    float val;
    if (i < 64 && j < 64) {
        const int r0 = 2 * i - 1;
        const int c0 = 2 * j - 1;
        float acc = 0.f;
        #pragma unroll
        for (int a = 0; a < 3; a++) {
            const int r = r0 + a;                    // <= 127
            if (r < 0) continue;
            const float wr = (a == 1) ? 0.5f : 0.25f;
            const float* row = sp + (size_t)r * 128;
            float l = (c0 >= 0) ? row[c0] : 0.f;
            float m = row[c0 + 1];
            float rt = row[c0 + 2];                  // <= 127
            acc += wr * hfilt(l, m, rt);
        }
        val = acc;
    } else {
        val = sp[(size_t)i * 128 + j];
    }
    out[(size_t)bc * H0 * W0C + (size_t)i * W0C + j] = val;
}

extern "C" void kernel_launch(void* const* d_in, const int* in_sizes, int n_in,
                              void* d_out, int out_size)
{
    (void)in_sizes; (void)n_in; (void)out_size;
    const float* x = (const float*)d_in[0];
    float* out = (float*)d_out;

    dim3 b(128);
    k1_copy_down0<<<dim3(1, 512, BC_TOTAL), b>>>(x, out);
    k2_down1     <<<dim3(1, 128, BC_TOTAL), b>>>(out);
    k3_down2     <<<dim3(1, 128, BC_TOTAL), b>>>(out);
}

// round 2
// speedup vs baseline: 1.4982x; 1.4982x over previous
#include <cuda_runtime.h>
#include <cuda_bf16.h>

// WaveletTransform: 3-level low-pass pyramid on x[8,32,512,512] fp32.
// out = x, except per-channel:
//   out[0:256,0:256] = down2x(conv3x3(x[0:512,0:512]))        (level 0)
//   out[0:128,0:128] = down2x(conv3x3(level0 result[0:256]^2)) (level 1)
//   out[0: 64,0: 64] = down2x(conv3x3(level1 result[0:128]^2)) (level 2)
// conv kernel = outer([.25,.5,.25],[.25,.5,.25]), zero-padded 'same',
// downsample takes even indices (center 2i,2j -> taps 2i-1..2i+1).
//
// R2: all conv paths use 2x aligned LDG.128 per row + __shfl_up for the
// single left-halo element (R1 ncu: L1tex 95% from scalar halo loads).

#define BC_TOTAL (8 * 32)
#define H0 512
#define W0C 512

__device__ float g_lvl1[BC_TOTAL * 128 * 128];

__device__ __forceinline__ float hfilt(float a, float b, float c) {
    return 0.25f * a + 0.5f * b + 0.25f * c;
}

// ---------------------------------------------------------------------------
// K1: fused identity copy (float4) + level-0 conv-down into top-left 256^2.
// grid (1,512,256), block 128. Thread j4 owns output cols 4j4..4j4+3.
// Conv warps (i<256, j4<64): per row load float4 pair cols [8j4, 8j4+8),
// left halo col 8j4-1 via shfl_up (lane 0: scalar load / zero-pad).
// ---------------------------------------------------------------------------
__global__ void __launch_bounds__(128) k1_copy_down0(
    const float* __restrict__ x, float* __restrict__ out)
{
    const int j4 = threadIdx.x;        // 0..127
    const int i  = blockIdx.y;         // 0..511
    const int bc = blockIdx.z;         // 0..255

    const float* xp = x   + (size_t)bc * H0 * W0C;
    float*       op = out + (size_t)bc * H0 * W0C;

    if (i < 256 && j4 < 64) {
        const int r0 = 2 * i - 1;                  // -1 only when i==0
        float acc0 = 0.f, acc1 = 0.f, acc2 = 0.f, acc3 = 0.f;
        #pragma unroll
        for (int a = 0; a < 3; a++) {
            const int r = r0 + a;                  // <= 511
            if (r < 0) continue;                   // uniform across warp
            const float wr = (a == 1) ? 0.5f : 0.25f;
            const float* row = xp + (size_t)r * W0C;
            const float4* rv = reinterpret_cast<const float4*>(row) + 2 * j4;
            float4 p0 = rv[0];
            float4 p1 = rv[1];
            float left = __shfl_up_sync(0xFFFFFFFFu, p1.w, 1);
            if ((j4 & 31) == 0)
                left = (j4 == 0) ? 0.f : row[8 * j4 - 1];
            acc0 += wr * hfilt(left, p0.x, p0.y);
            acc1 += wr * hfilt(p0.y, p0.z, p0.w);
            acc2 += wr * hfilt(p0.w, p1.x, p1.y);
            acc3 += wr * hfilt(p1.y, p1.z, p1.w);
        }
        *reinterpret_cast<float4*>(op + (size_t)i * W0C + 4 * j4) =
            make_float4(acc0, acc1, acc2, acc3);
    } else {
        const float4* src = reinterpret_cast<const float4*>(xp + (size_t)i * W0C) + j4;
        float4*       dst = reinterpret_cast<float4*>(op + (size_t)i * W0C) + j4;
        *dst = *src;
    }
}

// ---------------------------------------------------------------------------
// K2: level-1 conv-down. Reads out[0:256]^2 (row stride 512), writes 128^2
// to g_lvl1. block (32,4), grid (1,32,256). Thread j4 (=lane) owns out cols
// 4j4..4j4+3; warp spans the full 128-col row -> lane 0 is j4==0 (zero pad).
// ---------------------------------------------------------------------------
__global__ void __launch_bounds__(128) k2_down1(const float* __restrict__ out)
{
    const int j4 = threadIdx.x;                    // 0..31
    const int i  = blockIdx.y * 4 + threadIdx.y;   // 0..127
    const int bc = blockIdx.z;

    const float* sp = out + (size_t)bc * H0 * W0C; // level-0 region, stride 512
    const int r0 = 2 * i - 1;

    float acc0 = 0.f, acc1 = 0.f, acc2 = 0.f, acc3 = 0.f;
    #pragma unroll
    for (int a = 0; a < 3; a++) {
        const int r = r0 + a;                      // <= 255
        if (r < 0) continue;
        const float wr = (a == 1) ? 0.5f : 0.25f;
        const float* row = sp + (size_t)r * W0C;
        const float4* rv = reinterpret_cast<const float4*>(row) + 2 * j4;
        float4 p0 = rv[0];
        float4 p1 = rv[1];
        float left = __shfl_up_sync(0xFFFFFFFFu, p1.w, 1);
        if (j4 == 0) left = 0.f;
        acc0 += wr * hfilt(left, p0.x, p0.y);
        acc1 += wr * hfilt(p0.y, p0.z, p0.w);
        acc2 += wr * hfilt(p0.w, p1.x, p1.y);
        acc3 += wr * hfilt(p1.y, p1.z, p1.w);
    }
    *reinterpret_cast<float4*>(g_lvl1 + (size_t)bc * 128 * 128 +
                               (size_t)i * 128 + 4 * j4) =
        make_float4(acc0, acc1, acc2, acc3);
}

// ---------------------------------------------------------------------------
// K3: level-2 conv-down + writeback of the 128^2 region into out.
// block (32,4), grid (1,32,256). Thread j4 owns cols 4j4..4j4+3.
// Inner 64^2 (i<64, j4<16): conv-down of g_lvl1; else copy g_lvl1.
// ---------------------------------------------------------------------------
__global__ void __launch_bounds__(128) k3_down2(float* __restrict__ out)
{
    const int j4 = threadIdx.x;                    // 0..31
    const int i  = blockIdx.y * 4 + threadIdx.y;   // 0..127
    const int bc = blockIdx.z;

    const float* sp = g_lvl1 + (size_t)bc * 128 * 128;
    float4 val;

    if (i < 64 && j4 < 16) {
        const int r0 = 2 * i - 1;
        float acc0 = 0.f, acc1 = 0.f, acc2 = 0.f, acc3 = 0.f;
        #pragma unroll
        for (int a = 0; a < 3; a++) {
            const int r = r0 + a;                  // <= 127
            if (r < 0) continue;
            const float wr = (a == 1) ? 0.5f : 0.25f;
            const float* row = sp + (size_t)r * 128;
            const float4* rv = reinterpret_cast<const float4*>(row) + 2 * j4;
            float4 p0 = rv[0];
            float4 p1 = rv[1];                     // max col 8*15+7 = 127
            float left = __shfl_up_sync(0x0000FFFFu, p1.w, 1);
            if (j4 == 0) left = 0.f;
            acc0 += wr * hfilt(left, p0.x, p0.y);
            acc1 += wr * hfilt(p0.y, p0.z, p0.w);
            acc2 += wr * hfilt(p0.w, p1.x, p1.y);
            acc3 += wr * hfilt(p1.y, p1.z, p1.w);
        }
        val = make_float4(acc0, acc1, acc2, acc3);
    } else {
        val = *(reinterpret_cast<const float4*>(sp + (size_t)i * 128) + j4);
    }
    *reinterpret_cast<float4*>(out + (size_t)bc * H0 * W0C +
                               (size_t)i * W0C + 4 * j4) = val;
}

extern "C" void kernel_launch(void* const* d_in, const int* in_sizes, int n_in,
                              void* d_out, int out_size)
{
    (void)in_sizes; (void)n_in; (void)out_size;
    const float* x = (const float*)d_in[0];
    float* out = (float*)d_out;

    k1_copy_down0<<<dim3(1, 512, BC_TOTAL), dim3(128)>>>(x, out);
    k2_down1     <<<dim3(1, 32, BC_TOTAL), dim3(32, 4)>>>(out);
    k3_down2     <<<dim3(1, 32, BC_TOTAL), dim3(32, 4)>>>(out);
}

// round 3
// speedup vs baseline: 1.5847x; 1.0577x over previous
#include <cuda_runtime.h>
#include <cuda_bf16.h>

// WaveletTransform: 3-level low-pass pyramid on x[8,32,512,512] fp32.
// out = x, except per-channel:
//   out[0:256,0:256] = down2x(conv3x3(x[0:512,0:512]))        (level 0)
//   out[0:128,0:128] = down2x(conv3x3(level0 result[0:256]^2)) (level 1)
//   out[0: 64,0: 64] = down2x(conv3x3(level1 result[0:128]^2)) (level 2)
// conv kernel = outer([.25,.5,.25],[.25,.5,.25]), zero-padded 'same',
// downsample takes even indices (center 2i,2j -> taps 2i-1..2i+1).
//
// R2: conv paths use 2x aligned LDG.128 per row + __shfl_up for left halo.
// R3: K1 re-blocked to 8 rows / 256 threads per CTA (4 independent float4
//     load/store pairs per copy thread -> MLP 4, 8x fewer CTAs) and
//     streaming stores (__stcs) on the never-re-read copy region.

#define BC_TOTAL (8 * 32)
#define H0 512
#define W0C 512

__device__ float g_lvl1[BC_TOTAL * 128 * 128];

__device__ __forceinline__ float hfilt(float a, float b, float c) {
    return 0.25f * a + 0.5f * b + 0.25f * c;
}

// ---------------------------------------------------------------------------
// K1: fused identity copy + level-0 conv-down into top-left 256^2.
// grid (1,64,256), block 256. sub = tid>>7 selects a 4-row group; each thread
// owns column group j4 (float4) across 4 consecutive rows.
// Conv warps (rows<256, j4<64): 2x LDG.128 per input row + shfl left halo.
// Copy warps: 4 independent LDG.128 -> 4 STG.128.cs (region never re-read).
// ---------------------------------------------------------------------------
__global__ void __launch_bounds__(256) k1_copy_down0(
    const float* __restrict__ x, float* __restrict__ out)
{
    const int j4   = threadIdx.x & 127;          // 0..127 (col/4)
    const int sub  = threadIdx.x >> 7;           // 0..1
    const int base = blockIdx.y * 8 + sub * 4;   // first of 4 rows
    const int bc   = blockIdx.z;

    const float* xp = x   + (size_t)bc * H0 * W0C;
    float*       op = out + (size_t)bc * H0 * W0C;

    if (base < 256 && j4 < 64) {
        #pragma unroll
        for (int it = 0; it < 4; it++) {
            const int i  = base + it;
            const int r0 = 2 * i - 1;            // -1 only when i==0 (warp-uniform)
            float acc0 = 0.f, acc1 = 0.f, acc2 = 0.f, acc3 = 0.f;
            #pragma unroll
            for (int a = 0; a < 3; a++) {
                const int r = r0 + a;            // <= 511
                if (r < 0) continue;             // uniform across warp
                const float wr = (a == 1) ? 0.5f : 0.25f;
                const float* row = xp + (size_t)r * W0C;
                const float4* rv = reinterpret_cast<const float4*>(row) + 2 * j4;
                float4 p0 = rv[0];
                float4 p1 = rv[1];
                float left = __shfl_up_sync(0xFFFFFFFFu, p1.w, 1);
                if ((j4 & 31) == 0)
                    left = (j4 == 0) ? 0.f : row[8 * j4 - 1];
                acc0 += wr * hfilt(left, p0.x, p0.y);
                acc1 += wr * hfilt(p0.y, p0.z, p0.w);
                acc2 += wr * hfilt(p0.w, p1.x, p1.y);
                acc3 += wr * hfilt(p1.y, p1.z, p1.w);
            }
            *reinterpret_cast<float4*>(op + (size_t)i * W0C + 4 * j4) =
                make_float4(acc0, acc1, acc2, acc3);
        }
    } else {
        float4 v[4];
        #pragma unroll
        for (int it = 0; it < 4; it++)
            v[it] = *(reinterpret_cast<const float4*>(
                          xp + (size_t)(base + it) * W0C) + j4);
        #pragma unroll
        for (int it = 0; it < 4; it++)
            __stcs(reinterpret_cast<float4*>(
                       op + (size_t)(base + it) * W0C) + j4, v[it]);
    }
}

// ---------------------------------------------------------------------------
// K2: level-1 conv-down. Reads out[0:256]^2 (row stride 512), writes 128^2
// to g_lvl1. block (32,4), grid (1,32,256). Lane j4 owns out cols 4j4..4j4+3;
// warp spans the full 128-col row -> lane 0 is j4==0 (zero pad).
// ---------------------------------------------------------------------------
__global__ void __launch_bounds__(128) k2_down1(const float* __restrict__ out)
{
    const int j4 = threadIdx.x;                    // 0..31
    const int i  = blockIdx.y * 4 + threadIdx.y;   // 0..127
    const int bc = blockIdx.z;

    const float* sp = out + (size_t)bc * H0 * W0C; // level-0 region, stride 512
    const int r0 = 2 * i - 1;

    float acc0 = 0.f, acc1 = 0.f, acc2 = 0.f, acc3 = 0.f;
    #pragma unroll
    for (int a = 0; a < 3; a++) {
        const int r = r0 + a;                      // <= 255
        if (r < 0) continue;
        const float wr = (a == 1) ? 0.5f : 0.25f;
        const float* row = sp + (size_t)r * W0C;
        const float4* rv = reinterpret_cast<const float4*>(row) + 2 * j4;
        float4 p0 = rv[0];
        float4 p1 = rv[1];
        float left = __shfl_up_sync(0xFFFFFFFFu, p1.w, 1);
        if (j4 == 0) left = 0.f;
        acc0 += wr * hfilt(left, p0.x, p0.y);
        acc1 += wr * hfilt(p0.y, p0.z, p0.w);
        acc2 += wr * hfilt(p0.w, p1.x, p1.y);
        acc3 += wr * hfilt(p1.y, p1.z, p1.w);
    }
    *reinterpret_cast<float4*>(g_lvl1 + (size_t)bc * 128 * 128 +
                               (size_t)i * 128 + 4 * j4) =
        make_float4(acc0, acc1, acc2, acc3);
}

// ---------------------------------------------------------------------------
// K3: level-2 conv-down + writeback of the 128^2 region into out.
// block (32,4), grid (1,32,256). Thread j4 owns cols 4j4..4j4+3.
// Inner 64^2 (i<64, j4<16): conv-down of g_lvl1; else copy g_lvl1.
// ---------------------------------------------------------------------------
__global__ void __launch_bounds__(128) k3_down2(float* __restrict__ out)
{
    const int j4 = threadIdx.x;                    // 0..31
    const int i  = blockIdx.y * 4 + threadIdx.y;   // 0..127
    const int bc = blockIdx.z;

    const float* sp = g_lvl1 + (size_t)bc * 128 * 128;
    float4 val;

    if (i < 64 && j4 < 16) {
        const int r0 = 2 * i - 1;
        float acc0 = 0.f, acc1 = 0.f, acc2 = 0.f, acc3 = 0.f;
        #pragma unroll
        for (int a = 0; a < 3; a++) {
            const int r = r0 + a;                  // <= 127
            if (r < 0) continue;
            const float wr = (a == 1) ? 0.5f : 0.25f;
            const float* row = sp + (size_t)r * 128;
            const float4* rv = reinterpret_cast<const float4*>(row) + 2 * j4;
            float4 p0 = rv[0];
            float4 p1 = rv[1];                     // max col 8*15+7 = 127
            float left = __shfl_up_sync(0x0000FFFFu, p1.w, 1);
            if (j4 == 0) left = 0.f;
            acc0 += wr * hfilt(left, p0.x, p0.y);
            acc1 += wr * hfilt(p0.y, p0.z, p0.w);
            acc2 += wr * hfilt(p0.w, p1.x, p1.y);
            acc3 += wr * hfilt(p1.y, p1.z, p1.w);
        }
        val = make_float4(acc0, acc1, acc2, acc3);
    } else {
        val = *(reinterpret_cast<const float4*>(sp + (size_t)i * 128) + j4);
    }
    *reinterpret_cast<float4*>(out + (size_t)bc * H0 * W0C +
                               (size_t)i * W0C + 4 * j4) = val;
}

extern "C" void kernel_launch(void* const* d_in, const int* in_sizes, int n_in,
                              void* d_out, int out_size)
{
    (void)in_sizes; (void)n_in; (void)out_size;
    const float* x = (const float*)d_in[0];
    float* out = (float*)d_out;

    k1_copy_down0<<<dim3(1, 64, BC_TOTAL), dim3(256)>>>(x, out);
    k2_down1     <<<dim3(1, 32, BC_TOTAL), dim3(32, 4)>>>(out);
    k3_down2     <<<dim3(1, 32, BC_TOTAL), dim3(32, 4)>>>(out);
}

// round 4
// speedup vs baseline: 1.6535x; 1.0434x over previous
#include <cuda_runtime.h>
#include <cuda_bf16.h>

// WaveletTransform: 3-level low-pass pyramid on x[8,32,512,512] fp32.
// out = x, except per-channel:
//   out[0:256,0:256] = down2x(conv3x3(x[0:512,0:512]))        (level 0)
//   out[0:128,0:128] = down2x(conv3x3(level0 result[0:256]^2)) (level 1)
//   out[0: 64,0: 64] = down2x(conv3x3(level1 result[0:128]^2)) (level 2)
// conv kernel = outer([.25,.5,.25],[.25,.5,.25]), zero-padded 'same',
// downsample takes even indices (center 2i,2j -> taps 2i-1..2i+1).
//
// R2: conv paths use 2x aligned LDG.128 per row + __shfl_up for left halo.
// R3: K1 8 rows / 256 threads per CTA, streaming stores on copy region.
// R4: levels 1+2 fused into one CTA-per-channel kernel; level-1 lives in
//     dynamic smem (removes the 32MB g_lvl1 DRAM round-trip + one launch).

#define BC_TOTAL (8 * 32)
#define H0 512
#define W0C 512

#define L1_STRIDE 132                       // 128 + 4 floats pad (16B-aligned)
#define K23_SMEM (128 * L1_STRIDE * 4)      // 67584 bytes

__device__ __forceinline__ float hfilt(float a, float b, float c) {
    return 0.25f * a + 0.5f * b + 0.25f * c;
}

// ---------------------------------------------------------------------------
// K1: fused identity copy + level-0 conv-down into top-left 256^2.
// grid (1,64,256), block 256. sub = tid>>7 selects a 4-row group; each thread
// owns column group j4 (float4) across 4 consecutive rows.
// ---------------------------------------------------------------------------
__global__ void __launch_bounds__(256) k1_copy_down0(
    const float* __restrict__ x, float* __restrict__ out)
{
    const int j4   = threadIdx.x & 127;          // 0..127 (col/4)
    const int sub  = threadIdx.x >> 7;           // 0..1
    const int base = blockIdx.y * 8 + sub * 4;   // first of 4 rows
    const int bc   = blockIdx.z;

    const float* xp = x   + (size_t)bc * H0 * W0C;
    float*       op = out + (size_t)bc * H0 * W0C;

    if (base < 256 && j4 < 64) {
        #pragma unroll
        for (int it = 0; it < 4; it++) {
            const int i  = base + it;
            const int r0 = 2 * i - 1;            // -1 only when i==0
            float acc0 = 0.f, acc1 = 0.f, acc2 = 0.f, acc3 = 0.f;
            #pragma unroll
            for (int a = 0; a < 3; a++) {
                const int r = r0 + a;            // <= 511
                if (r < 0) continue;             // warp-uniform
                const float wr = (a == 1) ? 0.5f : 0.25f;
                const float* row = xp + (size_t)r * W0C;
                const float4* rv = reinterpret_cast<const float4*>(row) + 2 * j4;
                float4 p0 = rv[0];
                float4 p1 = rv[1];
                float left = __shfl_up_sync(0xFFFFFFFFu, p1.w, 1);
                if ((j4 & 31) == 0)
                    left = (j4 == 0) ? 0.f : row[8 * j4 - 1];
                acc0 += wr * hfilt(left, p0.x, p0.y);
                acc1 += wr * hfilt(p0.y, p0.z, p0.w);
                acc2 += wr * hfilt(p0.w, p1.x, p1.y);
                acc3 += wr * hfilt(p1.y, p1.z, p1.w);
            }
            *reinterpret_cast<float4*>(op + (size_t)i * W0C + 4 * j4) =
                make_float4(acc0, acc1, acc2, acc3);
        }
    } else {
        float4 v[4];
        #pragma unroll
        for (int it = 0; it < 4; it++)
            v[it] = *(reinterpret_cast<const float4*>(
                          xp + (size_t)(base + it) * W0C) + j4);
        #pragma unroll
        for (int it = 0; it < 4; it++)
            __stcs(reinterpret_cast<float4*>(
                       op + (size_t)(base + it) * W0C) + j4, v[it]);
    }
}

// ---------------------------------------------------------------------------
// K23: fused levels 1+2. One CTA per channel, 1024 threads, level-1 in smem.
// Phase 1: level-1 conv from out[0:256]^2 (stride 512) -> smem [128][132].
// Phase 2: out[0:128]^2 <- inner 64^2 conv of smem, remainder smem copy.
// Thread map: lane = col group (float4), wy = tid>>5 owns rows 4wy..4wy+3.
// ---------------------------------------------------------------------------
__global__ void __launch_bounds__(1024) k23_fused(float* __restrict__ out)
{
    extern __shared__ float l1[];               // [128][L1_STRIDE]
    const int lane = threadIdx.x & 31;
    const int wy   = threadIdx.x >> 5;          // 0..31
    const int bc   = blockIdx.x;

    float* op = out + (size_t)bc * H0 * W0C;

    // Phase 1: level-1 conv (reads level-0 result written by K1)
    #pragma unroll
    for (int it = 0; it < 4; it++) {
        const int i  = wy * 4 + it;             // 0..127
        const int r0 = 2 * i - 1;
        float acc0 = 0.f, acc1 = 0.f, acc2 = 0.f, acc3 = 0.f;
        #pragma unroll
        for (int a = 0; a < 3; a++) {
            const int r = r0 + a;               // <= 255
            if (r < 0) continue;                // warp-uniform
            const float wr = (a == 1) ? 0.5f : 0.25f;
            const float* row = op + (size_t)r * W0C;
            const float4* rv = reinterpret_cast<const float4*>(row) + 2 * lane;
            float4 p0 = rv[0];
            float4 p1 = rv[1];
            float left = __shfl_up_sync(0xFFFFFFFFu, p1.w, 1);
            if (lane == 0) left = 0.f;
            acc0 += wr * hfilt(left, p0.x, p0.y);
            acc1 += wr * hfilt(p0.y, p0.z, p0.w);
            acc2 += wr * hfilt(p0.w, p1.x, p1.y);
            acc3 += wr * hfilt(p1.y, p1.z, p1.w);
        }
        *reinterpret_cast<float4*>(&l1[i * L1_STRIDE + 4 * lane]) =
            make_float4(acc0, acc1, acc2, acc3);
    }
    __syncthreads();

    // Phase 2: level-2 conv (inner 64^2) + copy, write out[0:128]^2
    #pragma unroll
    for (int it = 0; it < 4; it++) {
        const int i = wy * 4 + it;              // 0..127
        float4 val;
        if (i < 64 && lane < 16) {
            const int r0 = 2 * i - 1;
            float acc0 = 0.f, acc1 = 0.f, acc2 = 0.f, acc3 = 0.f;
            #pragma unroll
            for (int a = 0; a < 3; a++) {
                const int r = r0 + a;           // <= 127
                if (r < 0) continue;
                const float wr = (a == 1) ? 0.5f : 0.25f;
                const float* row = &l1[r * L1_STRIDE];
                float4 p0 = *reinterpret_cast<const float4*>(row + 8 * lane);
                float4 p1 = *reinterpret_cast<const float4*>(row + 8 * lane + 4);
                float left = __shfl_up_sync(0x0000FFFFu, p1.w, 1);
                if (lane == 0) left = 0.f;
                acc0 += wr * hfilt(left, p0.x, p0.y);
                acc1 += wr * hfilt(p0.y, p0.z, p0.w);
                acc2 += wr * hfilt(p0.w, p1.x, p1.y);
                acc3 += wr * hfilt(p1.y, p1.z, p1.w);
            }
            val = make_float4(acc0, acc1, acc2, acc3);
        } else {
            val = *reinterpret_cast<const float4*>(&l1[i * L1_STRIDE + 4 * lane]);
        }
        *reinterpret_cast<float4*>(op + (size_t)i * W0C + 4 * lane) = val;
    }
}

extern "C" void kernel_launch(void* const* d_in, const int* in_sizes, int n_in,
                              void* d_out, int out_size)
{
    (void)in_sizes; (void)n_in; (void)out_size;
    const float* x = (const float*)d_in[0];
    float* out = (float*)d_out;

    static bool attr_set = false;
    if (!attr_set) {
        cudaFuncSetAttribute(k23_fused,
                             cudaFuncAttributeMaxDynamicSharedMemorySize,
                             K23_SMEM);
        attr_set = true;
    }

    k1_copy_down0<<<dim3(1, 64, BC_TOTAL), dim3(256)>>>(x, out);
    k23_fused    <<<dim3(BC_TOTAL), dim3(1024), K23_SMEM>>>(out);
}